// round 15
// baseline (speedup 1.0000x reference)
#include <cuda_runtime.h>
#include <cuda_bf16.h>

// MedSegNetV2: 3x3 texture features + martingale — register-rolling march,
// FULL 32-lane warps. Lane-task = one 8-px column segment x 8-row chunk;
// a warp takes 32 consecutive lane-tasks (spans chunk boundaries). Horizontal
// neighbors via shfl; warp-edge lanes use prefetched scalar LDG fixups.
// x: [8,64,224,224] f32 -> out: [8,256,224,224] f32, channel = c*4 + feature.

#define IMG_H 224
#define IMG_W 224
#define PLANE (IMG_H * IMG_W)
#define CH 8
#define CSEGS 28                  // 8-px column segments per row
#define CHUNKS (IMG_H / CH)       // 28
#define TASKS_PER_PLANE (CSEGS * CHUNKS)   // 784
#define PL0 (-1.3815511e-5f)      // 1e-6 * ln(1e-6)

#define MC   0.6065306597126334f          // exp(-0.5)
#define K1   ((8.0f / 9.0f) * MC)
#define KC0  (MC / 9e-6f)
#define KE   (MC / 9.0f)
#define KH   (9.0f * MC)

// Fetch row y (relative to this lane's plane/col): 2x LDG.128 + edge scalars.
#define FETCH(y) do {                                                         \
    const int _y = (y);                                                       \
    if ((unsigned)_y < IMG_H) {                                               \
        const float* _rp = base + (size_t)_y * IMG_W;                         \
        fa = *(const float4*)(_rp);                                           \
        fb = *(const float4*)(_rp + 4);                                       \
        if (fixL) fnl = __ldg(_rp - 1);                                       \
        if (fixR) fnr = __ldg(_rp + 8);                                       \
    } else {                                                                  \
        fa = make_float4(0.f, 0.f, 0.f, 0.f);                                 \
        fb = make_float4(0.f, 0.f, 0.f, 0.f);                                 \
        fnl = 0.f; fnr = 0.f;                                                 \
    }                                                                         \
} while (0)

// Consume fa/fb into ring slot s: raw values + plogp horizontal tri-sums.
#define ROWPROC(s) do {                                                       \
    float nl = __shfl_up_sync(FULL, fb.w, 1);                                 \
    if (fixL) nl = fnl;                                                       \
    if (csL)  nl = 0.f;                                                       \
    float nr = __shfl_down_sync(FULL, fa.x, 1);                               \
    if (fixR) nr = fnr;                                                       \
    if (csR)  nr = 0.f;                                                       \
    pr[s][0] = nl;   pr[s][1] = fa.x; pr[s][2] = fa.y; pr[s][3] = fa.z;       \
    pr[s][4] = fa.w; pr[s][5] = fb.x; pr[s][6] = fb.y; pr[s][7] = fb.z;       \
    pr[s][8] = fb.w; pr[s][9] = nr;                                           \
    float lo[10];                                                             \
    _Pragma("unroll")                                                         \
    for (int j = 1; j <= 8; j++) {                                            \
        const float c = fmaxf(pr[s][j], 1e-6f);                               \
        lo[j] = c * __logf(c);                                                \
    }                                                                         \
    lo[0] = __shfl_up_sync(FULL, lo[8], 1);                                   \
    lo[9] = __shfl_down_sync(FULL, lo[1], 1);                                 \
    if (csL) lo[0] = PL0;                                                     \
    if (lane == 0)  { const float c = fmaxf(nl, 1e-6f); lo[0] = c * __logf(c); } \
    if (csR) lo[9] = PL0;                                                     \
    if (lane == 31) { const float c = fmaxf(nr, 1e-6f); lo[9] = c * __logf(c); } \
    _Pragma("unroll")                                                         \
    for (int j = 0; j < 8; j++) hl[s][j] = lo[j] + lo[j + 1] + lo[j + 2];     \
} while (0)

// Emit one output row from ring slots s0,s1,s2; advances oc by one row.
#define OUTPUT(s0, s1, s2) do {                                               \
    float cS1[10], cS2[10];                                                   \
    _Pragma("unroll")                                                         \
    for (int j = 0; j < 10; j++) {                                            \
        cS1[j] = pr[s0][j] + pr[s1][j] + pr[s2][j];                           \
        cS2[j] = fmaf(pr[s0][j], pr[s0][j],                                   \
                 fmaf(pr[s1][j], pr[s1][j], pr[s2][j] * pr[s2][j]));          \
    }                                                                         \
    float m[8], g[8];                                                         \
    _Pragma("unroll")                                                         \
    for (int j = 0; j < 8; j++)                                               \
        m[j] = (cS1[j] + cS1[j + 1] + cS1[j + 2]) * (1.0f / 9.0f);            \
    _Pragma("unroll")                                                         \
    for (int j = 0; j < 8; j++) {                                             \
        const float S2 = cS2[j] + cS2[j + 1] + cS2[j + 2];                    \
        g[j] = fmaxf(S2 * KE, 1e-4f);                                         \
        cS2[j] = fmaf(-9.0f * m[j], m[j], S2);    /* reuse as M2 */           \
    }                                                                         \
    *(float4*)(oc + PLANE)     = make_float4(g[0], g[1], g[2], g[3]);         \
    *(float4*)(oc + PLANE + 4) = make_float4(g[4], g[5], g[6], g[7]);         \
    _Pragma("unroll")                                                         \
    for (int j = 0; j < 8; j++)                                               \
        g[j] = fminf(fmaxf(cS2[j] * KC0, 1e-4f), K1);                         \
    *(float4*)(oc)     = make_float4(g[0], g[1], g[2], g[3]);                 \
    *(float4*)(oc + 4) = make_float4(g[4], g[5], g[6], g[7]);                 \
    _Pragma("unroll")                                                         \
    for (int j = 0; j < 8; j++)                                               \
        g[j] = fmaxf((hl[s0][j] + hl[s1][j] + hl[s2][j]) * (-KE), 1e-4f);     \
    *(float4*)(oc + 2 * PLANE)     = make_float4(g[0], g[1], g[2], g[3]);     \
    *(float4*)(oc + 2 * PLANE + 4) = make_float4(g[4], g[5], g[6], g[7]);     \
    _Pragma("unroll")                                                         \
    for (int j = 0; j < 8; j++) {                                             \
        float sad = 0.f;                                                      \
        _Pragma("unroll")                                                     \
        for (int k = 0; k < 3; k++) {                                         \
            sad += fabsf(pr[s0][j + k] - m[j]);                               \
            sad += fabsf(pr[s1][j + k] - m[j]);                               \
            sad += fabsf(pr[s2][j + k] - m[j]);                               \
        }                                                                     \
        g[j] = fmaxf(KH * __frcp_rn(9.0f + sad + 9e-6f), 1e-4f);              \
    }                                                                         \
    *(float4*)(oc + 3 * PLANE)     = make_float4(g[0], g[1], g[2], g[3]);     \
    *(float4*)(oc + 3 * PLANE + 4) = make_float4(g[4], g[5], g[6], g[7]);     \
    oc += IMG_W;                                                              \
} while (0)

__global__ void __launch_bounds__(128, 5)
medseg12_kernel(const float* __restrict__ x, float* __restrict__ out) {
    const int lane = threadIdx.x & 31;
    const int wid = blockIdx.x * 4 + (threadIdx.x >> 5);
    const int t = wid * 32 + lane;                 // lane-task id
    const int colseg = t % CSEGS;
    const int rest = t / CSEGS;                    // plane*CHUNKS + chunk
    const int chunk = rest % CHUNKS;
    const int plane = rest / CHUNKS;
    const int ys = chunk * CH;
    const int col = colseg * 8;

    const bool csL  = (colseg == 0);               // image left border -> pad
    const bool csR  = (colseg == CSEGS - 1);       // image right border -> pad
    const bool fixL = (lane == 0)  && !csL;        // warp edge: LDG fixup
    const bool fixR = (lane == 31) && !csR;
    const unsigned FULL = 0xFFFFFFFFu;

    const float* __restrict__ base = x + (size_t)plane * PLANE + col;
    float* oc = out + (size_t)plane * 4 * PLANE + (size_t)ys * IMG_W + col;

    float pr[3][10];   // raw 3-row window ring
    float hl[3][8];    // plogp horizontal tri-sums ring
    float4 fa, fb;     // in-flight row
    float fnl, fnr;    // in-flight edge-fixup scalars

    // Prolog: rows ys-1, ys into slots 0,1; prefetch row ys+1.
    FETCH(ys - 1); ROWPROC(0);
    FETCH(ys);     ROWPROC(1);
    FETCH(ys + 1);

    // 8 output rows: 2 triple-steps + 2-step epilog.
    #pragma unroll 1
    for (int r = 0; r < 6; r += 3) {
        ROWPROC(2); FETCH(ys + r + 2); OUTPUT(0, 1, 2);
        ROWPROC(0); FETCH(ys + r + 3); OUTPUT(1, 2, 0);
        ROWPROC(1); FETCH(ys + r + 4); OUTPUT(2, 0, 1);
    }
    ROWPROC(2); FETCH(ys + 8); OUTPUT(0, 1, 2);
    ROWPROC(0);                OUTPUT(1, 2, 0);
}

extern "C" void kernel_launch(void* const* d_in, const int* in_sizes, int n_in,
                              void* d_out, int out_size) {
    const float* x = (const float*)d_in[0];
    float* out = (float*)d_out;
    // 512 planes * 784 lane-tasks = 401408 tasks = 12544 warps = 3136 blocks.
    medseg12_kernel<<<3136, 128>>>(x, out);
}

// round 16
// speedup vs baseline: 1.8395x; 1.8395x over previous
#include <cuda_runtime.h>
#include <cuda_bf16.h>

// MedSegNetV2: 3x3 texture features + martingale — register-rolling march.
// One warp = one full 224-wide row (28 lanes x 8 px), marching down an 8-row
// chunk of one plane. 3-row window in a register ring; no smem, no barriers.
// R16 = R14 base + log2-folded entropy, folded homog constant, streaming stores.
// x: [8,64,224,224] f32 -> out: [8,256,224,224] f32, channel = c*4 + feature.

#define IMG_H 224
#define IMG_W 224
#define PLANE (IMG_H * IMG_W)
#define CH 8
#define CHUNKS (IMG_H / CH)       // 28
#define PL2_0 (-1.9931569e-5f)    // 1e-6 * log2(1e-6)

#define MC   0.6065306597126334f          // exp(-0.5)
#define K1   ((8.0f / 9.0f) * MC)         // contrast ceiling (= value at threshold)
#define KC0  (MC / 9e-6f)                 // contrast tiny-variance slope
#define KE   (MC / 9.0f)                  // energy scale
#define KE2  ((MC * 0.6931471805599453f) / 9.0f)   // entropy scale (log2 domain)
#define KH   (9.0f * MC)

#define FETCH(y) do {                                                         \
    if ((unsigned)(y) < IMG_H) {                                              \
        fa = *(const float4*)(base + (size_t)(y) * IMG_W);                    \
        fb = *(const float4*)(base + (size_t)(y) * IMG_W + 4);                \
    } else {                                                                  \
        fa = make_float4(0.f, 0.f, 0.f, 0.f);                                 \
        fb = make_float4(0.f, 0.f, 0.f, 0.f);                                 \
    }                                                                         \
} while (0)

// Consume fa/fb (one image row) into ring slot s: raw values + plog2p tri-sums.
#define ROWPROC(s) do {                                                       \
    float nl = __shfl_up_sync(FULL, fb.w, 1);   if (L0)  nl = 0.f;            \
    float nr = __shfl_down_sync(FULL, fa.x, 1); if (R27) nr = 0.f;            \
    pr[s][0] = nl;   pr[s][1] = fa.x; pr[s][2] = fa.y; pr[s][3] = fa.z;       \
    pr[s][4] = fa.w; pr[s][5] = fb.x; pr[s][6] = fb.y; pr[s][7] = fb.z;       \
    pr[s][8] = fb.w; pr[s][9] = nr;                                           \
    float lo[10];                                                             \
    _Pragma("unroll")                                                         \
    for (int j = 1; j <= 8; j++) {                                            \
        const float c = fmaxf(pr[s][j], 1e-6f);                               \
        lo[j] = c * __log2f(c);                                               \
    }                                                                         \
    lo[0] = __shfl_up_sync(FULL, lo[8], 1);   if (L0)  lo[0] = PL2_0;         \
    lo[9] = __shfl_down_sync(FULL, lo[1], 1); if (R27) lo[9] = PL2_0;         \
    _Pragma("unroll")                                                         \
    for (int j = 0; j < 8; j++) hl[s][j] = lo[j] + lo[j + 1] + lo[j + 2];     \
} while (0)

// Emit one output row from ring slots s0,s1,s2; advances oc by one row.
#define OUTPUT(s0, s1, s2) do {                                               \
    float cS1[10], cS2[10];                                                   \
    _Pragma("unroll")                                                         \
    for (int j = 0; j < 10; j++) {                                            \
        cS1[j] = pr[s0][j] + pr[s1][j] + pr[s2][j];                           \
        cS2[j] = fmaf(pr[s0][j], pr[s0][j],                                   \
                 fmaf(pr[s1][j], pr[s1][j], pr[s2][j] * pr[s2][j]));          \
    }                                                                         \
    float m[8], g[8];                                                         \
    _Pragma("unroll")                                                         \
    for (int j = 0; j < 8; j++)                                               \
        m[j] = (cS1[j] + cS1[j + 1] + cS1[j + 2]) * (1.0f / 9.0f);            \
    _Pragma("unroll")                                                         \
    for (int j = 0; j < 8; j++) {                                             \
        const float S2 = cS2[j] + cS2[j + 1] + cS2[j + 2];                    \
        g[j] = fmaxf(S2 * KE, 1e-4f);                                         \
        cS2[j] = fmaf(-9.0f * m[j], m[j], S2);    /* reuse cS2[j] as M2 */    \
    }                                                                         \
    if (act) {                                                                \
        __stcs((float4*)(oc + PLANE),     make_float4(g[0], g[1], g[2], g[3]));\
        __stcs((float4*)(oc + PLANE + 4), make_float4(g[4], g[5], g[6], g[7]));\
    }                                                                         \
    _Pragma("unroll")                                                         \
    for (int j = 0; j < 8; j++)                                               \
        g[j] = fminf(fmaxf(cS2[j] * KC0, 1e-4f), K1);   /* contrast clamp */  \
    if (act) {                                                                \
        __stcs((float4*)(oc),     make_float4(g[0], g[1], g[2], g[3]));       \
        __stcs((float4*)(oc + 4), make_float4(g[4], g[5], g[6], g[7]));       \
    }                                                                         \
    _Pragma("unroll")                                                         \
    for (int j = 0; j < 8; j++)                                               \
        g[j] = fmaxf((hl[s0][j] + hl[s1][j] + hl[s2][j]) * (-KE2), 1e-4f);    \
    if (act) {                                                                \
        __stcs((float4*)(oc + 2 * PLANE),     make_float4(g[0], g[1], g[2], g[3]));\
        __stcs((float4*)(oc + 2 * PLANE + 4), make_float4(g[4], g[5], g[6], g[7]));\
    }                                                                         \
    _Pragma("unroll")                                                         \
    for (int j = 0; j < 8; j++) {                                             \
        float sad = 0.f;                                                      \
        _Pragma("unroll")                                                     \
        for (int k = 0; k < 3; k++) {                                         \
            sad += fabsf(pr[s0][j + k] - m[j]);                               \
            sad += fabsf(pr[s1][j + k] - m[j]);                               \
            sad += fabsf(pr[s2][j + k] - m[j]);                               \
        }                                                                     \
        g[j] = fmaxf(KH * __frcp_rn(sad + 9.000009f), 1e-4f);                 \
    }                                                                         \
    if (act) {                                                                \
        __stcs((float4*)(oc + 3 * PLANE),     make_float4(g[0], g[1], g[2], g[3]));\
        __stcs((float4*)(oc + 3 * PLANE + 4), make_float4(g[4], g[5], g[6], g[7]));\
    }                                                                         \
    oc += IMG_W;                                                              \
} while (0)

__global__ void __launch_bounds__(128, 5)
medseg13_kernel(const float* __restrict__ x, float* __restrict__ out) {
    const int lane = threadIdx.x & 31;
    const int task = blockIdx.x * 4 + (threadIdx.x >> 5);  // 14336 warp-tasks
    const int plane = task / CHUNKS;
    const int chunk = task - plane * CHUNKS;
    const int ys = chunk * CH;
    const int col = 8 * (lane < 28 ? lane : 27);
    const bool act = (lane < 28);
    const bool L0  = (lane == 0);
    const bool R27 = (lane >= 27);
    const unsigned FULL = 0xFFFFFFFFu;

    const float* __restrict__ base = x + (size_t)plane * PLANE + col;
    float* oc = out + (size_t)plane * 4 * PLANE + (size_t)ys * IMG_W + col;

    float pr[3][10];   // raw 3-row window ring
    float hl[3][8];    // plog2p horizontal tri-sums ring
    float4 fa, fb;     // in-flight row

    // Prolog: rows ys-1, ys into slots 0,1; prefetch row ys+1.
    FETCH(ys - 1); ROWPROC(0);
    FETCH(ys);     ROWPROC(1);
    FETCH(ys + 1);

    // 8 output rows: 2 triple-steps + 2-step epilog.
    #pragma unroll 1
    for (int r = 0; r < 6; r += 3) {
        ROWPROC(2); FETCH(ys + r + 2); OUTPUT(0, 1, 2);
        ROWPROC(0); FETCH(ys + r + 3); OUTPUT(1, 2, 0);
        ROWPROC(1); FETCH(ys + r + 4); OUTPUT(2, 0, 1);
    }
    ROWPROC(2); FETCH(ys + 8); OUTPUT(0, 1, 2);
    ROWPROC(0);                OUTPUT(1, 2, 0);
}

extern "C" void kernel_launch(void* const* d_in, const int* in_sizes, int n_in,
                              void* d_out, int out_size) {
    const float* x = (const float*)d_in[0];
    float* out = (float*)d_out;
    // 512 planes x 28 chunks = 14336 warp-tasks; 4 warps per 128-thread block.
    medseg13_kernel<<<14336 / 4, 128>>>(x, out);
}